// round 3
// baseline (speedup 1.0000x reference)
#include <cuda_runtime.h>
#include <math.h>

typedef unsigned long long ull;

#define BS 32
#define NRR 100
#define IND 2048
#define QDIM 1024
#define CCH 256
#define C1 128
#define C2 64

// ------------- scratch (device globals; no allocations) -------------
__device__ float g_Qp[BS * CCH];
__device__ float g_Xp[BS * NRR * CCH];
__device__ float g_logits[2 * BS * NRR * NRR];
__device__ float g_S[BS * NRR * NRR];

// ------------- f32x2 helpers -------------
__device__ __forceinline__ ull pack2(float x) {
    ull r; asm("mov.b64 %0, {%1,%1};" : "=l"(r) : "f"(x)); return r;
}
__device__ __forceinline__ ull fma2(ull a, ull b, ull c) {
    ull d; asm("fma.rn.f32x2 %0, %1, %2, %3;" : "=l"(d) : "l"(a), "l"(b), "l"(c)); return d;
}
__device__ __forceinline__ void unpack2(ull v, float& lo, float& hi) {
    asm("mov.b64 {%0,%1}, %2;" : "=f"(lo), "=f"(hi) : "l"(v));
}

// ================= K1: Qp = Q @ Wq + bq =================
__global__ void k1_qp(const float* __restrict__ Q, const float* __restrict__ Wq,
                      const float* __restrict__ bq) {
    __shared__ float qs[QDIM];
    int b = blockIdx.x, tid = threadIdx.x;
    for (int k = tid; k < QDIM; k += 256) qs[k] = Q[b * QDIM + k];
    __syncthreads();
    float a0 = 0.f, a1 = 0.f, a2 = 0.f, a3 = 0.f;
    for (int k = 0; k < QDIM; k += 4) {
        a0 += qs[k + 0] * Wq[(k + 0) * CCH + tid];
        a1 += qs[k + 1] * Wq[(k + 1) * CCH + tid];
        a2 += qs[k + 2] * Wq[(k + 2) * CCH + tid];
        a3 += qs[k + 3] * Wq[(k + 3) * CCH + tid];
    }
    g_Qp[b * CCH + tid] = bq[tid] + ((a0 + a1) + (a2 + a3));
}

// ================= K2: Xp = X @ Wv + bv + Qp[b] =================
// M=3200, N=256, K=2048. Tile 64x64, 256 threads, 4x4 micro.
__global__ __launch_bounds__(256) void k2_xp(const float* __restrict__ X,
                                             const float* __restrict__ Wv,
                                             const float* __restrict__ bv) {
    __shared__ float As[64][17];
    __shared__ float Bs[16][68];
    int tid = threadIdx.x;
    int m0 = blockIdx.y * 64, n0 = blockIdx.x * 64;
    int tx = tid & 15, ty = tid >> 4;
    int arow = tid >> 2, ak = (tid & 3) << 2;
    int bk = tid >> 4, bc = (tid & 15) << 2;
    float acc[4][4] = {};
    for (int kc = 0; kc < IND; kc += 16) {
        float4 av = *(const float4*)&X[(m0 + arow) * IND + kc + ak];
        float4 bw = *(const float4*)&Wv[(kc + bk) * CCH + n0 + bc];
        __syncthreads();
        As[arow][ak + 0] = av.x; As[arow][ak + 1] = av.y;
        As[arow][ak + 2] = av.z; As[arow][ak + 3] = av.w;
        *(float4*)&Bs[bk][bc] = bw;
        __syncthreads();
#pragma unroll
        for (int k = 0; k < 16; k++) {
            float a[4];
#pragma unroll
            for (int r = 0; r < 4; r++) a[r] = As[ty * 4 + r][k];
            float4 b4 = *(float4*)&Bs[k][tx * 4];
#pragma unroll
            for (int r = 0; r < 4; r++) {
                acc[r][0] += a[r] * b4.x; acc[r][1] += a[r] * b4.y;
                acc[r][2] += a[r] * b4.z; acc[r][3] += a[r] * b4.w;
            }
        }
    }
#pragma unroll
    for (int r = 0; r < 4; r++) {
        int m = m0 + ty * 4 + r;
        int bidx = m / NRR;
#pragma unroll
        for (int c = 0; c < 4; c++) {
            int n = n0 + tx * 4 + c;
            g_Xp[m * CCH + n] = acc[r][c] + bv[n] + g_Qp[bidx * CCH + n];
        }
    }
}

// ================= K3: fused pair-MLP (both branches) =================
// Tile: 16 i x 8 j = 128 pairs. Upper-tri tiles only (jt >= 2*it). 49 tiles/batch.
#define XIS 257
struct SM3 {
    float Xi[16 * XIS];
    float Xj[8 * XIS];
    float H1[128 * 129];
    float H2[128 * 65];
    float Ws[32 * 128];
    float W2s[128 * 64];
    float W3s[64];
};

__global__ __launch_bounds__(256, 1) void k3_pair(
    const float* __restrict__ W01, const float* __restrict__ b01,
    const float* __restrict__ W02, const float* __restrict__ b02,
    const float* __restrict__ W03, const float* __restrict__ b03,
    const float* __restrict__ W1, const float* __restrict__ b1,
    const float* __restrict__ W2, const float* __restrict__ b2,
    const float* __restrict__ W3, const float* __restrict__ b3) {
    extern __shared__ char raw[];
    SM3* sm = (SM3*)raw;
    int tid = threadIdx.x;
    int b = blockIdx.x / 49;
    int tile = blockIdx.x % 49;
    int it = 0, u = tile, cnt = 13;
    while (u >= cnt) { u -= cnt; it++; cnt -= 2; }
    int jt = 2 * it + u;
    int i0 = it * 16, j0 = jt * 8;

    // load Xi (16 rows), Xj (8 rows) of Xp[b]
    for (int t = tid; t < 16 * 256; t += 256) {
        int row = t >> 8, k = t & 255;
        int gi = i0 + row;
        sm->Xi[row * XIS + k] = (gi < NRR) ? g_Xp[(b * NRR + gi) * CCH + k] : 0.f;
    }
    for (int t = tid; t < 8 * 256; t += 256) {
        int row = t >> 8, k = t & 255;
        int gj = j0 + row;
        sm->Xj[row * XIS + k] = (gj < NRR) ? g_Xp[(b * NRR + gj) * CCH + k] : 0.f;
    }

    int rg = tid >> 4, cg = tid & 15;
    int c0 = cg * 8;

    for (int br = 0; br < 2; br++) {
        const float* Wa = br ? W1 : W01;  const float* ba = br ? b1 : b01;
        const float* Wb = br ? W2 : W02;  const float* bb = br ? b2 : b02;
        const float* Wc = br ? W3 : W03;  const float* bc = br ? b3 : b03;

        // ---- GEMM1: [128 pairs x 128] = P[128 x 256] @ Wa[256 x 128] ----
        ull acc[8][4];
#pragma unroll
        for (int r = 0; r < 8; r++)
#pragma unroll
            for (int n = 0; n < 4; n++) acc[r][n] = 0ULL;

        for (int kc = 0; kc < 8; kc++) {
            __syncthreads();
            for (int t = tid; t < 1024; t += 256)
                ((float4*)sm->Ws)[t] = ((const float4*)(Wa + kc * 4096))[t];
            __syncthreads();
#pragma unroll 4
            for (int k = 0; k < 32; k++) {
                int kk = kc * 32 + k;
                float xi = sm->Xi[rg * XIS + kk];
                ull a[8];
#pragma unroll
                for (int r = 0; r < 8; r++)
                    a[r] = pack2(xi * sm->Xj[r * XIS + kk]);
                ull bf[4];
#pragma unroll
                for (int n = 0; n < 4; n++)
                    bf[n] = *(const ull*)&sm->Ws[k * 128 + c0 + n * 2];
#pragma unroll
                for (int r = 0; r < 8; r++)
#pragma unroll
                    for (int n = 0; n < 4; n++)
                        acc[r][n] = fma2(a[r], bf[n], acc[r][n]);
            }
        }
        // epilogue: bias + relu -> H1; also stage W2s, W3s
        float bia[8];
#pragma unroll
        for (int t = 0; t < 8; t++) bia[t] = ba[c0 + t];
#pragma unroll
        for (int r = 0; r < 8; r++) {
            int m = rg * 8 + r;
#pragma unroll
            for (int n = 0; n < 4; n++) {
                float lo, hi; unpack2(acc[r][n], lo, hi);
                sm->H1[m * 129 + c0 + 2 * n]     = fmaxf(lo + bia[2 * n], 0.f);
                sm->H1[m * 129 + c0 + 2 * n + 1] = fmaxf(hi + bia[2 * n + 1], 0.f);
            }
        }
        for (int t = tid; t < 2048; t += 256)
            ((float4*)sm->W2s)[t] = ((const float4*)Wb)[t];
        if (tid < 64) sm->W3s[tid] = Wc[tid];
        __syncthreads();

        // ---- GEMM2: [128 x 64] = H1[128 x 128] @ Wb[128 x 64] ----
        ull acc2[8][2];
#pragma unroll
        for (int r = 0; r < 8; r++) { acc2[r][0] = 0ULL; acc2[r][1] = 0ULL; }
        int c20 = cg * 4;
#pragma unroll 4
        for (int k = 0; k < 128; k++) {
            ull b2v[2];
            b2v[0] = *(const ull*)&sm->W2s[k * 64 + c20];
            b2v[1] = *(const ull*)&sm->W2s[k * 64 + c20 + 2];
#pragma unroll
            for (int r = 0; r < 8; r++) {
                ull av = pack2(sm->H1[(rg * 8 + r) * 129 + k]);
                acc2[r][0] = fma2(av, b2v[0], acc2[r][0]);
                acc2[r][1] = fma2(av, b2v[1], acc2[r][1]);
            }
        }
        float bib[4];
#pragma unroll
        for (int t = 0; t < 4; t++) bib[t] = bb[c20 + t];
#pragma unroll
        for (int r = 0; r < 8; r++) {
            int m = rg * 8 + r;
#pragma unroll
            for (int n = 0; n < 2; n++) {
                float lo, hi; unpack2(acc2[r][n], lo, hi);
                sm->H2[m * 65 + c20 + 2 * n]     = fmaxf(lo + bib[2 * n], 0.f);
                sm->H2[m * 65 + c20 + 2 * n + 1] = fmaxf(hi + bib[2 * n + 1], 0.f);
            }
        }
        __syncthreads();

        // ---- GEMM3 + symmetric residual + logit write ----
        if (tid < 128) {
            int m = tid;
            float s = bc[0];
#pragma unroll 8
            for (int k = 0; k < 64; k++) s += sm->H2[m * 65 + k] * sm->W3s[k];
            float v = 2.f * fmaxf(s, 0.f);
            int i = i0 + (m >> 3), j = j0 + (m & 7);
            if (i < NRR && j < NRR) {
                float* L = g_logits + (br * BS + b) * (NRR * NRR);
                L[i * NRR + j] = v;
                L[j * NRR + i] = v;
            }
        }
    }
}

// ================= K4: softmax per (b,branch) + combine =================
__global__ void k4_softmax() {
    int b = blockIdx.x, tid = threadIdx.x;
    __shared__ float red[8];
    __shared__ float bm[2], bsum[2];
    const int NE = NRR * NRR;
    for (int br = 0; br < 2; br++) {
        const float* L = g_logits + (br * BS + b) * NE;
        float m = -1e30f;
        for (int e = tid; e < NE; e += 256) m = fmaxf(m, L[e]);
        for (int o = 16; o; o >>= 1) m = fmaxf(m, __shfl_xor_sync(~0u, m, o));
        if ((tid & 31) == 0) red[tid >> 5] = m;
        __syncthreads();
        if (tid == 0) {
            float a = red[0];
            for (int w = 1; w < 8; w++) a = fmaxf(a, red[w]);
            bm[br] = a;
        }
        __syncthreads();
        float mm = bm[br];
        float s = 0.f;
        for (int e = tid; e < NE; e += 256) s += expf(L[e] - mm);
        for (int o = 16; o; o >>= 1) s += __shfl_xor_sync(~0u, s, o);
        if ((tid & 31) == 0) red[tid >> 5] = s;
        __syncthreads();
        if (tid == 0) {
            float a = red[0];
            for (int w = 1; w < 8; w++) a += red[w];
            bsum[br] = a;
        }
        __syncthreads();
    }
    float m0 = bm[0], is0 = 1.f / bsum[0];
    float m1 = bm[1], is1 = 1.f / bsum[1];
    const float* L0 = g_logits + b * NE;
    const float* L1 = g_logits + (BS + b) * NE;
    float* S = g_S + b * NE;
    for (int e = tid; e < NE; e += 256)
        S[e] = 0.5f * (expf(L0[e] - m0) * is0 + expf(L1[e] - m1) * is1);
}

// ================= K5: out = S @ X * 0.5 (already halved in S combine? no) =================
// S already includes the (rm0+rm1)/2 factor (0.5 applied in k4), so out = S @ X.
__global__ __launch_bounds__(128) void k5_out(const float* __restrict__ X,
                                              float* __restrict__ out) {
    __shared__ float Ss[NRR * NRR];
    int b = blockIdx.y;
    int c0 = blockIdx.x * 512 + threadIdx.x * 4;
    for (int e = threadIdx.x; e < NRR * NRR; e += 128) Ss[e] = g_S[b * NRR * NRR + e];
    __syncthreads();
    const float* Xb = X + b * NRR * IND;
    for (int i0 = 0; i0 < NRR; i0 += 25) {
        float4 acc[25];
#pragma unroll
        for (int ii = 0; ii < 25; ii++) acc[ii] = make_float4(0.f, 0.f, 0.f, 0.f);
        for (int j = 0; j < NRR; j++) {
            float4 xv = *(const float4*)&Xb[j * IND + c0];
#pragma unroll
            for (int ii = 0; ii < 25; ii++) {
                float s = Ss[(i0 + ii) * NRR + j];
                acc[ii].x += s * xv.x; acc[ii].y += s * xv.y;
                acc[ii].z += s * xv.z; acc[ii].w += s * xv.w;
            }
        }
#pragma unroll
        for (int ii = 0; ii < 25; ii++)
            *(float4*)&out[(b * NRR + i0 + ii) * IND + c0] = acc[ii];
    }
}

// ================= launch =================
extern "C" void kernel_launch(void* const* d_in, const int* in_sizes, int n_in,
                              void* d_out, int out_size) {
    const float* Q   = (const float*)d_in[0];
    const float* X   = (const float*)d_in[1];
    const float* Wv  = (const float*)d_in[2];
    const float* bv  = (const float*)d_in[3];
    const float* Wq  = (const float*)d_in[4];
    const float* bq  = (const float*)d_in[5];
    const float* W01 = (const float*)d_in[6];
    const float* b01 = (const float*)d_in[7];
    const float* W02 = (const float*)d_in[8];
    const float* b02 = (const float*)d_in[9];
    const float* W03 = (const float*)d_in[10];
    const float* b03 = (const float*)d_in[11];
    const float* W1  = (const float*)d_in[12];
    const float* b1  = (const float*)d_in[13];
    const float* W2  = (const float*)d_in[14];
    const float* b2  = (const float*)d_in[15];
    const float* W3  = (const float*)d_in[16];
    const float* b3  = (const float*)d_in[17];
    float* out = (float*)d_out;

    cudaFuncSetAttribute(k3_pair, cudaFuncAttributeMaxDynamicSharedMemorySize,
                         (int)sizeof(SM3));

    k1_qp<<<BS, 256>>>(Q, Wq, bq);
    k2_xp<<<dim3(4, 50), 256>>>(X, Wv, bv);
    k3_pair<<<BS * 49, 256, sizeof(SM3)>>>(W01, b01, W02, b02, W03, b03,
                                           W1, b1, W2, b2, W3, b3);
    k4_softmax<<<BS, 256>>>();
    k5_out<<<dim3(4, BS), 128>>>(X, out);
}